// round 14
// baseline (speedup 1.0000x reference)
#include <cuda_runtime.h>

// Problem constants (x[8,512,8192], CHUNK=16, SE 512->64->512)
#define BB   8
#define CC   512
#define LL   8192
#define CS   16
#define NN   (LL / CS)     // 512 chunk positions
#define CH   (CC / 8)      // 64 bottleneck channels
#define NPG  32            // chunk positions per gate block (amortize weights)

// Static device scratch (no allocs allowed).
__device__ float g_e   [(size_t)BB * CC * NN];   // EMA output, 8 MB
__device__ float g_gate[(size_t)BB * CC * NN];   // gate, 8 MB
__device__ float g_w1t [(size_t)CC * CH];        // w1 transposed [c][o], 128 KB

// padded smem index: lane stride becomes 17 banks (conflict-free)
#define SPAD(i) ((i) + ((i) >> 4))

// gate kernel dynamic smem layout (in floats)
#define ES_W   (CC * NPG)                 // 16384 : e tile [c][j]
#define HP_STR 33                         // padded hidden-partial stride
#define HP_W   (2 * CH * HP_STR)          // 4224  : partials [cs][o][j]
#define HS_OFF (ES_W + HP_W)              // 20608
#define HS_W   (CH * NPG)                 // 2048  : final hidden [o][j]
#define GATE_SMEM_BYTES ((ES_W + HP_W + HS_W) * 4)   // 90624 B

// ---------------------------------------------------------------------------
// Kernel 1: chunked mean pooling + causal EMA per (b, c) row.
// grid = B*C = 4096 blocks, 256 threads. Coalesced; 4-lane shfl chunk sums.
// Blocks 0..127 additionally transpose w1 (consumed only by the gate kernel).
// ---------------------------------------------------------------------------
__global__ void __launch_bounds__(256) pool_ema_kernel(
    const float* __restrict__ x, const float* __restrict__ gamma,
    const float* __restrict__ w1)
{
    const int row = blockIdx.x;            // b*C + c
    const int c   = row & (CC - 1);
    const float g = gamma[c];
    const int t = threadIdx.x;

    if (blockIdx.x < (CC * CH) / 256) {
        const int i = blockIdx.x * 256 + t;
        int o = i / CC, cw = i % CC;       // w1 [CH][CC] -> w1t [CC][CH]
        g_w1t[(size_t)cw * CH + o] = w1[i];
    }

    __shared__ float s[NN + NN / 16];      // padded chunk means

    const float4* xr = reinterpret_cast<const float4*>(x) + (size_t)row * (LL / 4);

    float4 v[8];
#pragma unroll
    for (int k = 0; k < 8; k++)
        v[k] = xr[t + k * 256];            // 8 coalesced LDG.128 in flight

#pragma unroll
    for (int k = 0; k < 8; k++) {
        float r = (v[k].x + v[k].y) + (v[k].z + v[k].w);
        r += __shfl_down_sync(0xffffffffu, r, 2, 4);
        r += __shfl_down_sync(0xffffffffu, r, 1, 4);
        if ((t & 3) == 0) {
            int ci = (t >> 2) + k * 64;    // chunk index 0..511
            s[SPAD(ci)] = r * (1.0f / 16.0f);
        }
    }
    __syncthreads();

    if (t < 32) {
        const int lane = t;
        const float omg = 1.0f - g;

        float y = 0.f;
#pragma unroll
        for (int i = 0; i < 16; i++)
            y = fmaf(g, y, omg * s[lane * 17 + i]);      // SPAD(lane*16+i)
        float Bi = y;
        float g2 = g * g, g4 = g2 * g2, g8 = g4 * g4;
        float Ai = g8 * g8;

#pragma unroll
        for (int off = 1; off < 32; off <<= 1) {
            float a_up = __shfl_up_sync(0xffffffffu, Ai, off);
            float b_up = __shfl_up_sync(0xffffffffu, Bi, off);
            if (lane >= off) {
                Bi = fmaf(Ai, b_up, Bi);
                Ai = Ai * a_up;
            }
        }
        float prefix = __shfl_up_sync(0xffffffffu, Bi, 1);
        if (lane == 0) prefix = 0.f;

        float outv[16];
        y = prefix;
#pragma unroll
        for (int i = 0; i < 16; i++) {
            y = fmaf(g, y, omg * s[lane * 17 + i]);
            outv[i] = y;
        }
        float4* er = reinterpret_cast<float4*>(g_e + (size_t)row * NN + lane * 16);
#pragma unroll
        for (int i = 0; i < 4; i++)
            er[i] = make_float4(outv[4 * i], outv[4 * i + 1], outv[4 * i + 2], outv[4 * i + 3]);
    }
}

// ---------------------------------------------------------------------------
// Kernel 2: SE bottleneck -> sigmoid gate, weight-amortized.
// grid (NN/NPG = 16, B = 8) = 128 blocks, 512 threads, ~88 KB dynamic smem.
// Each block handles 32 chunk positions -> weight L2 traffic drops 4x and
// w1t/w2 (128 KB each) become L1-resident per SM.
// ---------------------------------------------------------------------------
__global__ void __launch_bounds__(512) se_gate_kernel(
    const float* __restrict__ w2,
    const float* __restrict__ b1, const float* __restrict__ b2)
{
    extern __shared__ float sm[];
    float* es = sm;                 // [CC][NPG]
    float* hp = sm + ES_W;          // [2][CH][HP_STR]
    float* hs = sm + HS_OFF;        // [CH][NPG]

    const int b  = blockIdx.y;
    const int n0 = blockIdx.x * NPG;
    const int tid = threadIdx.x;

    // ---- load e tile: 4096 float4 / 512 thr = 8 each ----
    const float4* ep = reinterpret_cast<const float4*>(
        g_e + ((size_t)b * CC) * NN + n0);
#pragma unroll
    for (int i = 0; i < 8; i++) {
        int f = tid + i * 512;                    // float4 idx = cc*8 + q
        int cc = f >> 3, q = f & 7;
        float4 v = ep[(size_t)cc * (NN / 4) + q];
        *reinterpret_cast<float4*>(&es[cc * NPG + q * 4]) = v;
    }
    __syncthreads();

    // ---- GEMM1 partials: thread = (q: 16 j-pairs, o4: 16 o-quads, cs: 2) ----
    {
        const int q  = tid & 15;          // j0 = q*2
        const int o4 = (tid >> 4) & 15;   // o = o4*4 .. +3
        const int cs = tid >> 8;          // c half
        const int j0 = q * 2;
        const int c0 = cs * 256;

        float a00 = 0.f, a01 = 0.f, a10 = 0.f, a11 = 0.f;
        float a20 = 0.f, a21 = 0.f, a30 = 0.f, a31 = 0.f;
        const float4* wp = reinterpret_cast<const float4*>(g_w1t) + o4;  // +cc*16
#pragma unroll 8
        for (int cc = c0; cc < c0 + 256; cc++) {
            float4 w = __ldg(wp + cc * (CH / 4));          // w1t[cc][o4*4..3]
            float2 e = *reinterpret_cast<const float2*>(&es[cc * NPG + j0]);
            a00 = fmaf(w.x, e.x, a00); a01 = fmaf(w.x, e.y, a01);
            a10 = fmaf(w.y, e.x, a10); a11 = fmaf(w.y, e.y, a11);
            a20 = fmaf(w.z, e.x, a20); a21 = fmaf(w.z, e.y, a21);
            a30 = fmaf(w.w, e.x, a30); a31 = fmaf(w.w, e.y, a31);
        }
        float* hpp = hp + cs * (CH * HP_STR) + (o4 * 4) * HP_STR + j0;
        hpp[0 * HP_STR] = a00; hpp[0 * HP_STR + 1] = a01;
        hpp[1 * HP_STR] = a10; hpp[1 * HP_STR + 1] = a11;
        hpp[2 * HP_STR] = a20; hpp[2 * HP_STR + 1] = a21;
        hpp[3 * HP_STR] = a30; hpp[3 * HP_STR + 1] = a31;
    }
    __syncthreads();

    // ---- reduce 2 c-halves + bias + relu -> hs[64][32] (4 per thread) ----
    {
        const int o = tid >> 3, j = (tid & 7) * 4;
        const float bb = b1[o];
#pragma unroll
        for (int d = 0; d < 4; d++) {
            float sum = hp[o * HP_STR + j + d]
                      + hp[CH * HP_STR + o * HP_STR + j + d];
            hs[o * NPG + j + d] = fmaxf(sum + bb, 0.f);
        }
    }
    __syncthreads();

    // ---- GEMM2: gate = sigmoid(W2 h + b2), one channel/thread, 4 j-passes ----
    {
        const int cch = tid;              // 0..511
        const float bb = b2[cch];
        const float4* wr = reinterpret_cast<const float4*>(w2 + (size_t)cch * CH);
        float4* gp = reinterpret_cast<float4*>(
            g_gate + ((size_t)b * CC + cch) * NN + n0);

#pragma unroll
        for (int p = 0; p < 4; p++) {     // j = p*8 .. +7
            float acc[8];
#pragma unroll
            for (int j = 0; j < 8; j++) acc[j] = 0.f;
#pragma unroll 4
            for (int k4 = 0; k4 < CH / 4; k4++) {
                float4 w = __ldg(wr + k4);        // L1-hit after pass 0
                const int k = k4 * 4;
#pragma unroll
                for (int i = 0; i < 4; i++) {
                    float wk = (i == 0) ? w.x : (i == 1) ? w.y : (i == 2) ? w.z : w.w;
                    const float* hrow = &hs[(k + i) * NPG + p * 8];   // broadcast
                    float4 h0 = *reinterpret_cast<const float4*>(hrow);
                    float4 h1 = *reinterpret_cast<const float4*>(hrow + 4);
                    acc[0] = fmaf(wk, h0.x, acc[0]); acc[1] = fmaf(wk, h0.y, acc[1]);
                    acc[2] = fmaf(wk, h0.z, acc[2]); acc[3] = fmaf(wk, h0.w, acc[3]);
                    acc[4] = fmaf(wk, h1.x, acc[4]); acc[5] = fmaf(wk, h1.y, acc[5]);
                    acc[6] = fmaf(wk, h1.z, acc[6]); acc[7] = fmaf(wk, h1.w, acc[7]);
                }
            }
            float4 o0, o1;
            o0.x = 1.0f / (1.0f + __expf(-(acc[0] + bb)));
            o0.y = 1.0f / (1.0f + __expf(-(acc[1] + bb)));
            o0.z = 1.0f / (1.0f + __expf(-(acc[2] + bb)));
            o0.w = 1.0f / (1.0f + __expf(-(acc[3] + bb)));
            o1.x = 1.0f / (1.0f + __expf(-(acc[4] + bb)));
            o1.y = 1.0f / (1.0f + __expf(-(acc[5] + bb)));
            o1.z = 1.0f / (1.0f + __expf(-(acc[6] + bb)));
            o1.w = 1.0f / (1.0f + __expf(-(acc[7] + bb)));
            gp[p * 2]     = o0;
            gp[p * 2 + 1] = o1;
        }
    }
}

// ---------------------------------------------------------------------------
// Kernel 3: out = gate * x, barrier-free pure stream.
// grid = 4096 blocks reversed vs pool. Gate distributed via shfl (no smem).
// x read-once (__ldcs), out streaming (__stcs).
// ---------------------------------------------------------------------------
__global__ void __launch_bounds__(256) apply_kernel(
    const float* __restrict__ x, float* __restrict__ out)
{
    const int row  = (BB * CC - 1) - blockIdx.x;      // reversed traversal
    const int t    = threadIdx.x;
    const int warp = t >> 5, lane = t & 31;

    const float* grow = g_gate + (size_t)row * NN;
    const float4* xr  = reinterpret_cast<const float4*>(x)  + (size_t)row * (LL / 4);
    float4*       orr = reinterpret_cast<float4*>(out)      + (size_t)row * (LL / 4);

    float4 v[8];
    float  gk[8];
#pragma unroll
    for (int k = 0; k < 8; k++) {
        v[k]  = __ldcs(xr + t + k * 256);
        gk[k] = grow[warp * 8 + (lane & 7) + k * 64];  // lanes 0..7 hold 8 chunks
    }
#pragma unroll
    for (int k = 0; k < 8; k++) {
        float gv = __shfl_sync(0xffffffffu, gk[k], lane >> 2);
        v[k].x *= gv; v[k].y *= gv; v[k].z *= gv; v[k].w *= gv;
        __stcs(orr + t + k * 256, v[k]);
    }
}

// ---------------------------------------------------------------------------
// kernel_launch: inputs in metadata order: x, gamma, w1, b1, w2, b2
// ---------------------------------------------------------------------------
extern "C" void kernel_launch(void* const* d_in, const int* in_sizes, int n_in,
                              void* d_out, int out_size)
{
    const float* x     = (const float*)d_in[0];
    const float* gamma = (const float*)d_in[1];
    const float* w1    = (const float*)d_in[2];
    const float* b1    = (const float*)d_in[3];
    const float* w2    = (const float*)d_in[4];
    const float* b2    = (const float*)d_in[5];
    float* out = (float*)d_out;

    // idempotent, host-side attribute (not a stream op; capture-legal)
    static bool attr_set = false;
    if (!attr_set) {
        cudaFuncSetAttribute(se_gate_kernel,
                             cudaFuncAttributeMaxDynamicSharedMemorySize,
                             GATE_SMEM_BYTES);
        attr_set = true;
    }

    pool_ema_kernel<<<BB * CC, 256>>>(x, gamma, w1);

    dim3 gridG(NN / NPG, BB);
    se_gate_kernel<<<gridG, 512, GATE_SMEM_BYTES>>>(w2, b1, b2);

    apply_kernel<<<BB * CC, 256>>>(x, out);
}

// round 15
// speedup vs baseline: 1.5967x; 1.5967x over previous
#include <cuda_runtime.h>

// Problem constants (x[8,512,8192], CHUNK=16, SE 512->64->512)
#define BB   8
#define CC   512
#define LL   8192
#define CS   16
#define NN   (LL / CS)     // 512 chunk positions
#define CH   (CC / 8)      // 64 bottleneck channels
#define NT   8             // chunk positions per block in h/gate kernels

// Static device scratch (no allocs allowed).
__device__ float g_e   [(size_t)BB * CC * NN];   // EMA output, 8 MB
__device__ float g_gate[(size_t)BB * CC * NN];   // gate, 8 MB
__device__ float g_h   [(size_t)BB * CH * NN];   // hidden h[b][o][n], 1 MB
__device__ float g_w1t [(size_t)CC * CH];        // w1 transposed [c][o], 128 KB
__device__ float g_w2t [(size_t)CH * CC];        // w2 transposed [k][c], 128 KB

// padded smem index: lane stride becomes 17 banks (conflict-free)
#define SPAD(i) ((i) + ((i) >> 4))

// ---------------------------------------------------------------------------
// Kernel 1: chunked mean pooling + causal EMA per (b, c) row.
// grid = B*C = 4096 blocks, 256 threads. Coalesced; 4-lane shfl chunk sums.
// Blocks 0..127 additionally transpose w1 AND w2 (consumed only later).
// ---------------------------------------------------------------------------
__global__ void __launch_bounds__(256) pool_ema_kernel(
    const float* __restrict__ x, const float* __restrict__ gamma,
    const float* __restrict__ w1, const float* __restrict__ w2)
{
    const int row = blockIdx.x;            // b*C + c
    const int c   = row & (CC - 1);
    const float g = gamma[c];
    const int t = threadIdx.x;

    if (blockIdx.x < (CC * CH) / 256) {
        const int i = blockIdx.x * 256 + t;
        {   // w1 [CH][CC] -> w1t [CC][CH]
            int o = i / CC, cw = i % CC;
            g_w1t[(size_t)cw * CH + o] = w1[i];
        }
        {   // w2 [CC][CH] -> w2t [CH][CC]
            int cw = i / CH, k = i % CH;
            g_w2t[(size_t)k * CC + cw] = w2[i];
        }
    }

    __shared__ float s[NN + NN / 16];      // padded chunk means

    const float4* xr = reinterpret_cast<const float4*>(x) + (size_t)row * (LL / 4);

    float4 v[8];
#pragma unroll
    for (int k = 0; k < 8; k++)
        v[k] = xr[t + k * 256];            // 8 coalesced LDG.128 in flight

#pragma unroll
    for (int k = 0; k < 8; k++) {
        float r = (v[k].x + v[k].y) + (v[k].z + v[k].w);
        r += __shfl_down_sync(0xffffffffu, r, 2, 4);
        r += __shfl_down_sync(0xffffffffu, r, 1, 4);
        if ((t & 3) == 0) {
            int ci = (t >> 2) + k * 64;    // chunk index 0..511
            s[SPAD(ci)] = r * (1.0f / 16.0f);
        }
    }
    __syncthreads();

    if (t < 32) {
        const int lane = t;
        const float omg = 1.0f - g;

        float y = 0.f;
#pragma unroll
        for (int i = 0; i < 16; i++)
            y = fmaf(g, y, omg * s[lane * 17 + i]);      // SPAD(lane*16+i)
        float Bi = y;
        float g2 = g * g, g4 = g2 * g2, g8 = g4 * g4;
        float Ai = g8 * g8;

#pragma unroll
        for (int off = 1; off < 32; off <<= 1) {
            float a_up = __shfl_up_sync(0xffffffffu, Ai, off);
            float b_up = __shfl_up_sync(0xffffffffu, Bi, off);
            if (lane >= off) {
                Bi = fmaf(Ai, b_up, Bi);
                Ai = Ai * a_up;
            }
        }
        float prefix = __shfl_up_sync(0xffffffffu, Bi, 1);
        if (lane == 0) prefix = 0.f;

        float outv[16];
        y = prefix;
#pragma unroll
        for (int i = 0; i < 16; i++) {
            y = fmaf(g, y, omg * s[lane * 17 + i]);
            outv[i] = y;
        }
        float4* er = reinterpret_cast<float4*>(g_e + (size_t)row * NN + lane * 16);
#pragma unroll
        for (int i = 0; i < 4; i++)
            er[i] = make_float4(outv[4 * i], outv[4 * i + 1], outv[4 * i + 2], outv[4 * i + 3]);
    }
}

// ---------------------------------------------------------------------------
// Kernel 2a: h = relu(W1 e + b1) only.
// grid (NN/NT = 64, B = 8) = 512 blocks, 256 threads.
// Thread = (q: j-pair, o4: 4 o-channels, cs: 4-way c-split of 128).
// inner iter: 1 LDG.128(w1t) + 1 LDS.64(e) -> 8 FMA.
// ---------------------------------------------------------------------------
__global__ void __launch_bounds__(256) se_h_kernel(const float* __restrict__ b1)
{
    const int b  = blockIdx.y;
    const int n0 = blockIdx.x * NT;
    const int tid = threadIdx.x;

    __shared__ float es[CC][NT];        // 16 KB e tile
    __shared__ float hpart[4][CH][9];   // 9.2 KB padded partials

    // ---- load e tile: 1024 float4 / 256 thr = 4 each ----
    const float4* ep = reinterpret_cast<const float4*>(
        g_e + ((size_t)b * CC) * NN + n0);
#pragma unroll
    for (int i = 0; i < 4; i++) {
        int idx = tid + i * 256;                 // = cc*2 + q
        int cc = idx >> 1, q = idx & 1;
        float4 v = ep[(size_t)cc * (NN / 4) + q];
        *reinterpret_cast<float4*>(&es[cc][q * 4]) = v;
    }
    __syncthreads();

    // ---- GEMM1 register-blocked partials ----
    const int q  = tid & 3;          // j0 = q*2
    const int o4 = (tid >> 2) & 15;  // o = o4*4 .. +3
    const int cs = tid >> 6;         // c in [cs*128, cs*128+128)
    const int j0 = q * 2;
    {
        const int c0 = cs * 128;
        float a00 = 0.f, a01 = 0.f, a10 = 0.f, a11 = 0.f;
        float a20 = 0.f, a21 = 0.f, a30 = 0.f, a31 = 0.f;
        const float4* wp = reinterpret_cast<const float4*>(g_w1t) + o4;  // +cc*16
#pragma unroll 8
        for (int cc = c0; cc < c0 + 128; cc++) {
            float4 w = __ldg(wp + cc * (CH / 4));     // w1t[cc][o4*4..3]
            float2 e = *reinterpret_cast<const float2*>(&es[cc][j0]);
            a00 = fmaf(w.x, e.x, a00); a01 = fmaf(w.x, e.y, a01);
            a10 = fmaf(w.y, e.x, a10); a11 = fmaf(w.y, e.y, a11);
            a20 = fmaf(w.z, e.x, a20); a21 = fmaf(w.z, e.y, a21);
            a30 = fmaf(w.w, e.x, a30); a31 = fmaf(w.w, e.y, a31);
        }
        float* hp = &hpart[cs][o4 * 4][0];
        hp[0 * 9 + j0] = a00; hp[0 * 9 + j0 + 1] = a01;
        hp[1 * 9 + j0] = a10; hp[1 * 9 + j0 + 1] = a11;
        hp[2 * 9 + j0] = a20; hp[2 * 9 + j0 + 1] = a21;
        hp[3 * 9 + j0] = a30; hp[3 * 9 + j0 + 1] = a31;
    }
    __syncthreads();

    // ---- reduce 4 c-splits + bias + relu -> g_h, thread = (o = tid>>2, j0) ----
    {
        const int o = tid >> 2;
        const float bb = b1[o];
        float s0 = hpart[0][o][j0] + hpart[1][o][j0]
                 + hpart[2][o][j0] + hpart[3][o][j0];
        float s1 = hpart[0][o][j0 + 1] + hpart[1][o][j0 + 1]
                 + hpart[2][o][j0 + 1] + hpart[3][o][j0 + 1];
        float2 hv;
        hv.x = fmaxf(s0 + bb, 0.f);
        hv.y = fmaxf(s1 + bb, 0.f);
        *reinterpret_cast<float2*>(g_h + ((size_t)b * CH + o) * NN + n0 + j0) = hv;
    }
}

// ---------------------------------------------------------------------------
// Kernel 2b: gate = sigmoid(W2 h + b2). No C-reduction constraint -> channels
// split across blocks: grid (NN/NT = 64, B*4 = 32) = 2048 blocks, 128 threads.
// Per block: stage h tile [64][NT] (2 KB), then 64 coalesced w2t LDG.32 each.
// ---------------------------------------------------------------------------
__global__ void __launch_bounds__(128) se_gate2_kernel(const float* __restrict__ b2)
{
    const int b  = blockIdx.y >> 2;          // batch
    const int cq = blockIdx.y & 3;           // channel quarter
    const int n0 = blockIdx.x * NT;
    const int tid = threadIdx.x;

    __shared__ float hs[CH][NT];             // 2 KB h tile

    // ---- stage h tile: 128 float4 / 128 thr = 1 each ----
    {
        int k = tid >> 1, q = tid & 1;       // k channel, float4 half
        float4 v = *reinterpret_cast<const float4*>(
            g_h + ((size_t)b * CH + k) * NN + n0 + q * 4);
        *reinterpret_cast<float4*>(&hs[k][q * 4]) = v;
    }
    __syncthreads();

    // ---- GEMM2: one output channel per thread ----
    {
        const int cch = cq * 128 + tid;
        float acc[NT];
#pragma unroll
        for (int j = 0; j < NT; j++) acc[j] = 0.f;
#pragma unroll 8
        for (int k = 0; k < CH; k++) {
            float w = __ldg(g_w2t + (size_t)k * CC + cch);   // lane stride 4B
            float4 h0 = *reinterpret_cast<const float4*>(&hs[k][0]);
            float4 h1 = *reinterpret_cast<const float4*>(&hs[k][4]);
            acc[0] = fmaf(w, h0.x, acc[0]); acc[1] = fmaf(w, h0.y, acc[1]);
            acc[2] = fmaf(w, h0.z, acc[2]); acc[3] = fmaf(w, h0.w, acc[3]);
            acc[4] = fmaf(w, h1.x, acc[4]); acc[5] = fmaf(w, h1.y, acc[5]);
            acc[6] = fmaf(w, h1.z, acc[6]); acc[7] = fmaf(w, h1.w, acc[7]);
        }
        const float bb = b2[cch];
        float4 o0, o1;
        o0.x = 1.0f / (1.0f + __expf(-(acc[0] + bb)));
        o0.y = 1.0f / (1.0f + __expf(-(acc[1] + bb)));
        o0.z = 1.0f / (1.0f + __expf(-(acc[2] + bb)));
        o0.w = 1.0f / (1.0f + __expf(-(acc[3] + bb)));
        o1.x = 1.0f / (1.0f + __expf(-(acc[4] + bb)));
        o1.y = 1.0f / (1.0f + __expf(-(acc[5] + bb)));
        o1.z = 1.0f / (1.0f + __expf(-(acc[6] + bb)));
        o1.w = 1.0f / (1.0f + __expf(-(acc[7] + bb)));
        float4* gp = reinterpret_cast<float4*>(
            g_gate + ((size_t)b * CC + cch) * NN + n0);
        gp[0] = o0;
        gp[1] = o1;
    }
}

// ---------------------------------------------------------------------------
// Kernel 3: out = gate * x, barrier-free pure stream.
// grid = 4096 blocks reversed vs pool. Gate distributed via shfl (no smem).
// x read-once (__ldcs), out streaming (__stcs).
// ---------------------------------------------------------------------------
__global__ void __launch_bounds__(256) apply_kernel(
    const float* __restrict__ x, float* __restrict__ out)
{
    const int row  = (BB * CC - 1) - blockIdx.x;      // reversed traversal
    const int t    = threadIdx.x;
    const int warp = t >> 5, lane = t & 31;

    const float* grow = g_gate + (size_t)row * NN;
    const float4* xr  = reinterpret_cast<const float4*>(x)  + (size_t)row * (LL / 4);
    float4*       orr = reinterpret_cast<float4*>(out)      + (size_t)row * (LL / 4);

    float4 v[8];
    float  gk[8];
#pragma unroll
    for (int k = 0; k < 8; k++) {
        v[k]  = __ldcs(xr + t + k * 256);
        gk[k] = grow[warp * 8 + (lane & 7) + k * 64];  // lanes 0..7 hold 8 chunks
    }
#pragma unroll
    for (int k = 0; k < 8; k++) {
        float gv = __shfl_sync(0xffffffffu, gk[k], lane >> 2);
        v[k].x *= gv; v[k].y *= gv; v[k].z *= gv; v[k].w *= gv;
        __stcs(orr + t + k * 256, v[k]);
    }
}

// ---------------------------------------------------------------------------
// kernel_launch: inputs in metadata order: x, gamma, w1, b1, w2, b2
// ---------------------------------------------------------------------------
extern "C" void kernel_launch(void* const* d_in, const int* in_sizes, int n_in,
                              void* d_out, int out_size)
{
    const float* x     = (const float*)d_in[0];
    const float* gamma = (const float*)d_in[1];
    const float* w1    = (const float*)d_in[2];
    const float* b1    = (const float*)d_in[3];
    const float* w2    = (const float*)d_in[4];
    const float* b2    = (const float*)d_in[5];
    float* out = (float*)d_out;

    pool_ema_kernel<<<BB * CC, 256>>>(x, gamma, w1, w2);

    dim3 gridH(NN / NT, BB);
    se_h_kernel<<<gridH, 256>>>(b1);

    dim3 gridG(NN / NT, BB * 4);
    se_gate2_kernel<<<gridG, 128>>>(b2);

    apply_kernel<<<BB * CC, 256>>>(x, out);
}

// round 16
// speedup vs baseline: 1.7588x; 1.1015x over previous
#include <cuda_runtime.h>

// Problem constants (x[8,512,8192], CHUNK=16, SE 512->64->512)
#define BB   8
#define CC   512
#define LL   8192
#define CS   16
#define NN   (LL / CS)     // 512 chunk positions
#define CH   (CC / 8)      // 64 bottleneck channels
#define NT   8             // chunk positions per block (se_h and apply tiles)

// Static device scratch (no allocs allowed).
__device__ float g_e   [(size_t)BB * CC * NN];   // EMA output, 8 MB
__device__ float g_h   [(size_t)BB * CH * NN];   // hidden h[b][o][n], 1 MB
__device__ float g_w1t [(size_t)CC * CH];        // w1 transposed [c][o], 128 KB
__device__ float g_w2t [(size_t)CH * CC];        // w2 transposed [k][c], 128 KB

// padded smem index: lane stride becomes 17 banks (conflict-free)
#define SPAD(i) ((i) + ((i) >> 4))

// ---------------------------------------------------------------------------
// Kernel 1: chunked mean pooling + causal EMA per (b, c) row.
// grid = B*C = 4096 blocks, 256 threads. Coalesced; 4-lane shfl chunk sums.
// Blocks 0..127 additionally transpose w1 AND w2 (consumed only later).
// ---------------------------------------------------------------------------
__global__ void __launch_bounds__(256) pool_ema_kernel(
    const float* __restrict__ x, const float* __restrict__ gamma,
    const float* __restrict__ w1, const float* __restrict__ w2)
{
    const int row = blockIdx.x;            // b*C + c
    const int c   = row & (CC - 1);
    const float g = gamma[c];
    const int t = threadIdx.x;

    if (blockIdx.x < (CC * CH) / 256) {
        const int i = blockIdx.x * 256 + t;
        {   // w1 [CH][CC] -> w1t [CC][CH]
            int o = i / CC, cw = i % CC;
            g_w1t[(size_t)cw * CH + o] = w1[i];
        }
        {   // w2 [CC][CH] -> w2t [CH][CC]
            int cw = i / CH, k = i % CH;
            g_w2t[(size_t)k * CC + cw] = w2[i];
        }
    }

    __shared__ float s[NN + NN / 16];      // padded chunk means

    const float4* xr = reinterpret_cast<const float4*>(x) + (size_t)row * (LL / 4);

    float4 v[8];
#pragma unroll
    for (int k = 0; k < 8; k++)
        v[k] = xr[t + k * 256];            // 8 coalesced LDG.128 in flight

#pragma unroll
    for (int k = 0; k < 8; k++) {
        float r = (v[k].x + v[k].y) + (v[k].z + v[k].w);
        r += __shfl_down_sync(0xffffffffu, r, 2, 4);
        r += __shfl_down_sync(0xffffffffu, r, 1, 4);
        if ((t & 3) == 0) {
            int ci = (t >> 2) + k * 64;    // chunk index 0..511
            s[SPAD(ci)] = r * (1.0f / 16.0f);
        }
    }
    __syncthreads();

    if (t < 32) {
        const int lane = t;
        const float omg = 1.0f - g;

        float y = 0.f;
#pragma unroll
        for (int i = 0; i < 16; i++)
            y = fmaf(g, y, omg * s[lane * 17 + i]);      // SPAD(lane*16+i)
        float Bi = y;
        float g2 = g * g, g4 = g2 * g2, g8 = g4 * g4;
        float Ai = g8 * g8;

#pragma unroll
        for (int off = 1; off < 32; off <<= 1) {
            float a_up = __shfl_up_sync(0xffffffffu, Ai, off);
            float b_up = __shfl_up_sync(0xffffffffu, Bi, off);
            if (lane >= off) {
                Bi = fmaf(Ai, b_up, Bi);
                Ai = Ai * a_up;
            }
        }
        float prefix = __shfl_up_sync(0xffffffffu, Bi, 1);
        if (lane == 0) prefix = 0.f;

        float outv[16];
        y = prefix;
#pragma unroll
        for (int i = 0; i < 16; i++) {
            y = fmaf(g, y, omg * s[lane * 17 + i]);
            outv[i] = y;
        }
        float4* er = reinterpret_cast<float4*>(g_e + (size_t)row * NN + lane * 16);
#pragma unroll
        for (int i = 0; i < 4; i++)
            er[i] = make_float4(outv[4 * i], outv[4 * i + 1], outv[4 * i + 2], outv[4 * i + 3]);
    }
}

// ---------------------------------------------------------------------------
// Kernel 2: h = relu(W1 e + b1) only.
// grid (NN/NT = 64, B = 8) = 512 blocks, 256 threads.
// Thread = (q: j-pair, o4: 4 o-channels, cs: 4-way c-split of 128).
// inner iter: 1 LDG.128(w1t) + 1 LDS.64(e) -> 8 FMA.
// ---------------------------------------------------------------------------
__global__ void __launch_bounds__(256) se_h_kernel(const float* __restrict__ b1)
{
    const int b  = blockIdx.y;
    const int n0 = blockIdx.x * NT;
    const int tid = threadIdx.x;

    __shared__ float es[CC][NT];        // 16 KB e tile
    __shared__ float hpart[4][CH][9];   // 9.2 KB padded partials

    // ---- load e tile: 1024 float4 / 256 thr = 4 each ----
    const float4* ep = reinterpret_cast<const float4*>(
        g_e + ((size_t)b * CC) * NN + n0);
#pragma unroll
    for (int i = 0; i < 4; i++) {
        int idx = tid + i * 256;                 // = cc*2 + q
        int cc = idx >> 1, q = idx & 1;
        float4 v = ep[(size_t)cc * (NN / 4) + q];
        *reinterpret_cast<float4*>(&es[cc][q * 4]) = v;
    }
    __syncthreads();

    // ---- GEMM1 register-blocked partials ----
    const int q  = tid & 3;          // j0 = q*2
    const int o4 = (tid >> 2) & 15;  // o = o4*4 .. +3
    const int cs = tid >> 6;         // c in [cs*128, cs*128+128)
    const int j0 = q * 2;
    {
        const int c0 = cs * 128;
        float a00 = 0.f, a01 = 0.f, a10 = 0.f, a11 = 0.f;
        float a20 = 0.f, a21 = 0.f, a30 = 0.f, a31 = 0.f;
        const float4* wp = reinterpret_cast<const float4*>(g_w1t) + o4;  // +cc*16
#pragma unroll 8
        for (int cc = c0; cc < c0 + 128; cc++) {
            float4 w = __ldg(wp + cc * (CH / 4));     // w1t[cc][o4*4..3]
            float2 e = *reinterpret_cast<const float2*>(&es[cc][j0]);
            a00 = fmaf(w.x, e.x, a00); a01 = fmaf(w.x, e.y, a01);
            a10 = fmaf(w.y, e.x, a10); a11 = fmaf(w.y, e.y, a11);
            a20 = fmaf(w.z, e.x, a20); a21 = fmaf(w.z, e.y, a21);
            a30 = fmaf(w.w, e.x, a30); a31 = fmaf(w.w, e.y, a31);
        }
        float* hp = &hpart[cs][o4 * 4][0];
        hp[0 * 9 + j0] = a00; hp[0 * 9 + j0 + 1] = a01;
        hp[1 * 9 + j0] = a10; hp[1 * 9 + j0 + 1] = a11;
        hp[2 * 9 + j0] = a20; hp[2 * 9 + j0 + 1] = a21;
        hp[3 * 9 + j0] = a30; hp[3 * 9 + j0 + 1] = a31;
    }
    __syncthreads();

    // ---- reduce 4 c-splits + bias + relu -> g_h, thread = (o = tid>>2, j0) ----
    {
        const int o = tid >> 2;
        const float bb = b1[o];
        float s0 = hpart[0][o][j0] + hpart[1][o][j0]
                 + hpart[2][o][j0] + hpart[3][o][j0];
        float s1 = hpart[0][o][j0 + 1] + hpart[1][o][j0 + 1]
                 + hpart[2][o][j0 + 1] + hpart[3][o][j0 + 1];
        float2 hv;
        hv.x = fmaxf(s0 + bb, 0.f);
        hv.y = fmaxf(s1 + bb, 0.f);
        *reinterpret_cast<float2*>(g_h + ((size_t)b * CH + o) * NN + n0 + j0) = hv;
    }
}

// ---------------------------------------------------------------------------
// Kernel 3: FUSED gate (GEMM2+sigmoid) + apply.
// grid (NN/NT = 64, B = 8) = 512 blocks (reversed), 512 threads.
// Phase 1: stage h tile [64][8] (2 KB).
// Phase 2: thread = channel -> gate[cch][0..7] via 64 coalesced w2t loads.
// Phase 3: stream the 512 x NT*16 timestep x tile (16384 float4), gate from smem.
// ---------------------------------------------------------------------------
__global__ void __launch_bounds__(512) gate_apply_kernel(
    const float* __restrict__ x, const float* __restrict__ b2,
    float* __restrict__ out)
{
    const int blk = (gridDim.x * gridDim.y - 1) - (blockIdx.y * gridDim.x + blockIdx.x);
    const int b   = blk >> 6;                 // batch (reversed order)
    const int nt  = blk & 63;                 // n-tile
    const int n0  = nt * NT;
    const int tid = threadIdx.x;

    __shared__ float hs[CH][NT];              // 2 KB h tile
    __shared__ float gs[CC][NT];              // 16 KB gate tile

    // ---- phase 1: stage h tile (128 float4) ----
    if (tid < 128) {
        int k = tid >> 1, q = tid & 1;
        float4 v = *reinterpret_cast<const float4*>(
            g_h + ((size_t)b * CH + k) * NN + n0 + q * 4);
        *reinterpret_cast<float4*>(&hs[k][q * 4]) = v;
    }
    __syncthreads();

    // ---- phase 2: gate[cch][j] = sigmoid(w2t[:,cch].h + b2) ----
    {
        const int cch = tid;                  // 0..511
        float acc[NT];
#pragma unroll
        for (int j = 0; j < NT; j++) acc[j] = 0.f;
#pragma unroll 8
        for (int k = 0; k < CH; k++) {
            float w = __ldg(g_w2t + (size_t)k * CC + cch);   // lane-coalesced
            float4 h0 = *reinterpret_cast<const float4*>(&hs[k][0]);
            float4 h1 = *reinterpret_cast<const float4*>(&hs[k][4]);
            acc[0] = fmaf(w, h0.x, acc[0]); acc[1] = fmaf(w, h0.y, acc[1]);
            acc[2] = fmaf(w, h0.z, acc[2]); acc[3] = fmaf(w, h0.w, acc[3]);
            acc[4] = fmaf(w, h1.x, acc[4]); acc[5] = fmaf(w, h1.y, acc[5]);
            acc[6] = fmaf(w, h1.z, acc[6]); acc[7] = fmaf(w, h1.w, acc[7]);
        }
        const float bb = b2[cch];
#pragma unroll
        for (int j = 0; j < NT; j++)
            gs[cch][j] = 1.0f / (1.0f + __expf(-(acc[j] + bb)));
    }
    __syncthreads();

    // ---- phase 3: stream x tile: 512 rows x 32 float4 (cols n0*4 .. +32) ----
    const size_t base = ((size_t)b * CC) * (LL / 4) + (size_t)nt * 32;
    const float4* xp = reinterpret_cast<const float4*>(x) + base;
    float4*       op = reinterpret_cast<float4*>(out)     + base;

#pragma unroll
    for (int ii = 0; ii < 4; ii++) {
        float4 v[8];
        int idx0 = tid + ii * 4096;           // 8 loads of 512-thread strides
#pragma unroll
        for (int j = 0; j < 8; j++) {
            int idx = idx0 + j * 512;         // = c*32 + col
            int c = idx >> 5, col = idx & 31;
            v[j] = __ldcs(xp + (size_t)c * (LL / 4) + col);
        }
#pragma unroll
        for (int j = 0; j < 8; j++) {
            int idx = idx0 + j * 512;
            int c = idx >> 5, col = idx & 31;
            float gv = gs[c][col >> 2];       // 4 float4 per chunk
            v[j].x *= gv; v[j].y *= gv; v[j].z *= gv; v[j].w *= gv;
            __stcs(op + (size_t)c * (LL / 4) + col, v[j]);
        }
    }
}

// ---------------------------------------------------------------------------
// kernel_launch: inputs in metadata order: x, gamma, w1, b1, w2, b2
// ---------------------------------------------------------------------------
extern "C" void kernel_launch(void* const* d_in, const int* in_sizes, int n_in,
                              void* d_out, int out_size)
{
    const float* x     = (const float*)d_in[0];
    const float* gamma = (const float*)d_in[1];
    const float* w1    = (const float*)d_in[2];
    const float* b1    = (const float*)d_in[3];
    const float* w2    = (const float*)d_in[4];
    const float* b2    = (const float*)d_in[5];
    float* out = (float*)d_out;

    pool_ema_kernel<<<BB * CC, 256>>>(x, gamma, w1, w2);

    dim3 gridH(NN / NT, BB);
    se_h_kernel<<<gridH, 256>>>(b1);

    dim3 gridA(NN / NT, BB);
    gate_apply_kernel<<<gridA, 512>>>(x, b2, out);
}